// round 2
// baseline (speedup 1.0000x reference)
#include <cuda_runtime.h>
#include <math.h>

#define DIM 128

// Scratch: aggregation buffer [N, DIM] and sigmoid(rel) gate [R, DIM].
__device__ float g_agg[100000 * DIM];
__device__ float g_gate[500 * DIM];

// ---------------------------------------------------------------------------
// Kernel 1: zero the aggregation buffer (float4 grid-stride).
// ---------------------------------------------------------------------------
__global__ void zero_agg_kernel(int n4) {
    int i = blockIdx.x * blockDim.x + threadIdx.x;
    float4 z = make_float4(0.f, 0.f, 0.f, 0.f);
    for (; i < n4; i += gridDim.x * blockDim.x) {
        ((float4*)g_agg)[i] = z;
    }
}

// ---------------------------------------------------------------------------
// Kernel 2: per relation row: gate = sigmoid(rel), out_rel = rel @ W_rel^T + b_rel.
// One block (128 threads) per relation row.
// ---------------------------------------------------------------------------
__global__ void rel_kernel(const float* __restrict__ rel,
                           const float* __restrict__ W_rel,
                           const float* __restrict__ b_rel,
                           float* __restrict__ out_rel) {
    __shared__ float srow[DIM];
    int r = blockIdx.x;
    int t = threadIdx.x;

    float x = rel[r * DIM + t];
    srow[t] = x;
    g_gate[r * DIM + t] = 1.f / (1.f + expf(-x));
    __syncthreads();

    float acc = b_rel[t];
    const float4* w4 = (const float4*)&W_rel[t * DIM];
#pragma unroll
    for (int k4 = 0; k4 < DIM / 4; k4++) {
        float4 w = w4[k4];
        float4 xx = *(const float4*)&srow[k4 * 4];
        acc += w.x * xx.x + w.y * xx.y + w.z * xx.z + w.w * xx.w;
    }
    out_rel[r * DIM + t] = acc;
}

// ---------------------------------------------------------------------------
// Kernel 3: edge gather -> gate -> scatter-add.
// One warp per edge; each lane handles one float4.
// NOTE: edge_index / edge_type arrive as int32 (harness converts int64).
// ---------------------------------------------------------------------------
__global__ void edge_kernel(const float* __restrict__ ent,
                            const int* __restrict__ eidx,
                            const int* __restrict__ etype,
                            int E) {
    int warp = (blockIdx.x * blockDim.x + threadIdx.x) >> 5;
    int lane = threadIdx.x & 31;
    if (warp >= E) return;

    int src = eidx[warp];
    int dst = eidx[E + warp];
    int t   = etype[warp];

    float4 e4 = ((const float4*)ent)[src * 32 + lane];
    float4 g4 = ((const float4*)g_gate)[t * 32 + lane];
    float4 m;
    m.x = e4.x * g4.x;
    m.y = e4.y * g4.y;
    m.z = e4.z * g4.z;
    m.w = e4.w * g4.w;

    float* p = &g_agg[dst * DIM + lane * 4];
    asm volatile("red.global.add.v4.f32 [%0], {%1, %2, %3, %4};"
                 :: "l"(p), "f"(m.x), "f"(m.y), "f"(m.z), "f"(m.w)
                 : "memory");
}

// ---------------------------------------------------------------------------
// Kernel 4: fused GEMM  out = relu(ent @ W_self^T + agg @ W_nei^T + b_self + b_nei)
// Combined K = 256. 64 rows per block, 256 threads.
// ---------------------------------------------------------------------------
#define GEMM_ROWS 64
#define WPAD 132
#define WTC_WORDS (256 * WPAD)
#define XT_WORDS  (GEMM_ROWS * 256)
#define GEMM_SMEM_BYTES ((WTC_WORDS + XT_WORDS) * 4)

__global__ void __launch_bounds__(256, 1)
gemm_ent_kernel(const float* __restrict__ ent,
                const float* __restrict__ W_self,
                const float* __restrict__ b_self,
                const float* __restrict__ W_nei,
                const float* __restrict__ b_nei,
                float* __restrict__ out,
                int N) {
    extern __shared__ float sm[];
    float* Wtc = sm;                 // [256][WPAD]
    float* xt  = sm + WTC_WORDS;     // [64][256]

    int tid = threadIdx.x;

    // Transposed combined weights: Wtc[k][o] = W[o][k].
    for (int i = tid; i < DIM * DIM; i += 256) {
        int o = i >> 7;
        int k = i & 127;
        Wtc[k * WPAD + o]         = W_self[i];
        Wtc[(k + 128) * WPAD + o] = W_nei[i];
    }

    // x tile: xt[r][0..127] = ent row, xt[r][128..255] = agg row.
    int row0 = blockIdx.x * GEMM_ROWS;
    for (int i = tid; i < GEMM_ROWS * 32; i += 256) {
        int r = i >> 5;
        int c = i & 31;
        int row = row0 + r;
        float4 e = make_float4(0.f, 0.f, 0.f, 0.f);
        float4 a = make_float4(0.f, 0.f, 0.f, 0.f);
        if (row < N) {
            e = ((const float4*)ent)[row * 32 + c];
            a = ((const float4*)g_agg)[row * 32 + c];
        }
        ((float4*)&xt[r * 256])[c]       = e;
        ((float4*)&xt[r * 256 + 128])[c] = a;
    }
    __syncthreads();

    int warp = tid >> 5;
    int lane = tid & 31;
    int r0 = warp * 8;
    int o  = lane * 4;

    float bias[4];
#pragma unroll
    for (int j = 0; j < 4; j++) bias[j] = b_self[o + j] + b_nei[o + j];

    float acc[8][4];
#pragma unroll
    for (int r = 0; r < 8; r++)
#pragma unroll
        for (int j = 0; j < 4; j++) acc[r][j] = bias[j];

    for (int k4 = 0; k4 < 64; k4++) {
        float4 xv[8];
#pragma unroll
        for (int r = 0; r < 8; r++)
            xv[r] = *(const float4*)&xt[(r0 + r) * 256 + k4 * 4];
#pragma unroll
        for (int kk = 0; kk < 4; kk++) {
            float4 w = *(const float4*)&Wtc[(k4 * 4 + kk) * WPAD + o];
#pragma unroll
            for (int r = 0; r < 8; r++) {
                float xvk = (kk == 0) ? xv[r].x : (kk == 1) ? xv[r].y
                          : (kk == 2) ? xv[r].z : xv[r].w;
                acc[r][0] += xvk * w.x;
                acc[r][1] += xvk * w.y;
                acc[r][2] += xvk * w.z;
                acc[r][3] += xvk * w.w;
            }
        }
    }

#pragma unroll
    for (int r = 0; r < 8; r++) {
        int row = row0 + r0 + r;
        if (row < N) {
            float4 v;
            v.x = fmaxf(acc[r][0], 0.f);
            v.y = fmaxf(acc[r][1], 0.f);
            v.z = fmaxf(acc[r][2], 0.f);
            v.w = fmaxf(acc[r][3], 0.f);
            ((float4*)out)[row * 32 + lane] = v;
        }
    }
}

// ---------------------------------------------------------------------------
// Launch. Inputs (metadata order): ent, rel, edge_index(int32 [2,E]),
// edge_type(int32 [E]), W_self, b_self, W_nei, b_nei, W_rel, b_rel.
// Output: out_ent [N,128] then out_rel [R,128].
// ---------------------------------------------------------------------------
extern "C" void kernel_launch(void* const* d_in, const int* in_sizes, int n_in,
                              void* d_out, int out_size) {
    const float* ent    = (const float*)d_in[0];
    const float* rel    = (const float*)d_in[1];
    const int* eidx     = (const int*)d_in[2];
    const int* etype    = (const int*)d_in[3];
    const float* W_self = (const float*)d_in[4];
    const float* b_self = (const float*)d_in[5];
    const float* W_nei  = (const float*)d_in[6];
    const float* b_nei  = (const float*)d_in[7];
    const float* W_rel  = (const float*)d_in[8];
    const float* b_rel  = (const float*)d_in[9];

    int N = in_sizes[0] / DIM;   // 100000
    int R = in_sizes[1] / DIM;   // 500
    int E = in_sizes[3];         // 600000

    float* out_ent = (float*)d_out;
    float* out_rel = (float*)d_out + (size_t)N * DIM;

    int n4 = N * (DIM / 4);
    zero_agg_kernel<<<1024, 256>>>(n4);

    rel_kernel<<<R, DIM>>>(rel, W_rel, b_rel, out_rel);

    int edge_blocks = (E * 32 + 255) / 256;
    edge_kernel<<<edge_blocks, 256>>>(ent, eidx, etype, E);

    static int smem_set = 0;
    if (!smem_set) {
        cudaFuncSetAttribute(gemm_ent_kernel,
                             cudaFuncAttributeMaxDynamicSharedMemorySize,
                             GEMM_SMEM_BYTES);
        smem_set = 1;
    }
    int gemm_blocks = (N + GEMM_ROWS - 1) / GEMM_ROWS;
    gemm_ent_kernel<<<gemm_blocks, 256, GEMM_SMEM_BYTES>>>(
        ent, W_self, b_self, W_nei, b_nei, out_ent, N);
}

// round 4
// speedup vs baseline: 2.1745x; 2.1745x over previous
#include <cuda_runtime.h>
#include <math.h>
#include <stdint.h>

#define DIM 128

// Scratch: aggregation buffer [N, DIM] and sigmoid(rel) gate [R, DIM].
__device__ float g_agg[100000 * DIM];
__device__ float g_gate[500 * DIM];

__device__ __forceinline__ uint32_t smem_u32(const void* p) {
    uint32_t a;
    asm("{ .reg .u64 t; cvta.to.shared.u64 t, %1; cvt.u32.u64 %0, t; }"
        : "=r"(a) : "l"(p));
    return a;
}

__device__ __forceinline__ uint32_t f2tf32(float x) {
    uint32_t t;
    asm("cvt.rna.tf32.f32 %0, %1;" : "=r"(t) : "f"(x));
    return t;
}

// ============================================================================
// Kernel 1: zero the aggregation buffer.
// ============================================================================
__global__ void zero_agg_kernel(int n4) {
    int i = blockIdx.x * blockDim.x + threadIdx.x;
    float4 z = make_float4(0.f, 0.f, 0.f, 0.f);
    for (; i < n4; i += gridDim.x * blockDim.x) {
        ((float4*)g_agg)[i] = z;
    }
}

// ============================================================================
// Kernel 2: gate = sigmoid(rel), out_rel = rel @ W_rel^T + b_rel.
// ============================================================================
__global__ void rel_kernel(const float* __restrict__ rel,
                           const float* __restrict__ W_rel,
                           const float* __restrict__ b_rel,
                           float* __restrict__ out_rel) {
    __shared__ float srow[DIM];
    int r = blockIdx.x;
    int t = threadIdx.x;

    float x = rel[r * DIM + t];
    srow[t] = x;
    g_gate[r * DIM + t] = 1.f / (1.f + expf(-x));
    __syncthreads();

    float acc = b_rel[t];
    const float4* w4 = (const float4*)&W_rel[t * DIM];
#pragma unroll
    for (int k4 = 0; k4 < DIM / 4; k4++) {
        float4 w = w4[k4];
        float4 xx = *(const float4*)&srow[k4 * 4];
        acc += w.x * xx.x + w.y * xx.y + w.z * xx.z + w.w * xx.w;
    }
    out_rel[r * DIM + t] = acc;
}

// ============================================================================
// Kernel 3: edge gather -> gate -> scatter-add (warp per edge, REDG.128/lane).
// ============================================================================
__global__ void edge_kernel(const float* __restrict__ ent,
                            const int* __restrict__ eidx,
                            const int* __restrict__ etype,
                            int E) {
    int warp = (blockIdx.x * blockDim.x + threadIdx.x) >> 5;
    int lane = threadIdx.x & 31;
    if (warp >= E) return;

    int src = eidx[warp];
    int dst = eidx[E + warp];
    int t   = etype[warp];

    float4 e4 = ((const float4*)ent)[src * 32 + lane];
    float4 g4 = ((const float4*)g_gate)[t * 32 + lane];
    float4 m;
    m.x = e4.x * g4.x;
    m.y = e4.y * g4.y;
    m.z = e4.z * g4.z;
    m.w = e4.w * g4.w;

    float* p = &g_agg[dst * DIM + lane * 4];
    asm volatile("red.global.add.v4.f32 [%0], {%1, %2, %3, %4};"
                 :: "l"(p), "f"(m.x), "f"(m.y), "f"(m.z), "f"(m.w)
                 : "memory");
}

// ============================================================================
// Kernel 4: tf32 mma.sync GEMM
//   out = relu( X @ Wc^T + bias ),  X = [ent | agg] (K=256), Wc = [W_self|W_nei]
// Block tile 128x128, K chunks of 32, cp.async double buffer.
// 8 warps (2x4), warp tile m64 x n32 via mma.m16n8k8 tf32.
// SMEM pitch 36 floats: bank = (4*row + col) % 32 -> conflict-free fragments.
// ============================================================================
#define PITCH 36
#define TILE_BYTES (128 * PITCH * 4)   // 18432
#define SM_AS(b)  ((b) * TILE_BYTES)
#define SM_BS(b)  (2 * TILE_BYTES + (b) * TILE_BYTES)
#define SM_BIAS   (4 * TILE_BYTES)     // 73728
#define GEMM_SMEM (4 * TILE_BYTES + 512)

#define CP_ASYNC(dst, src, sz) \
    asm volatile("cp.async.ca.shared.global [%0], [%1], 16, %2;" \
                 :: "r"(dst), "l"(src), "r"(sz) : "memory")
#define CP_COMMIT() asm volatile("cp.async.commit_group;" ::: "memory")
#define CP_WAIT(n)  asm volatile("cp.async.wait_group %0;" :: "n"(n) : "memory")

__device__ __forceinline__ void mma_tf32(float* c, const uint32_t* a,
                                         const uint32_t* b) {
    asm volatile(
        "mma.sync.aligned.m16n8k8.row.col.f32.tf32.tf32.f32 "
        "{%0,%1,%2,%3}, {%4,%5,%6,%7}, {%8,%9}, {%0,%1,%2,%3};"
        : "+f"(c[0]), "+f"(c[1]), "+f"(c[2]), "+f"(c[3])
        : "r"(a[0]), "r"(a[1]), "r"(a[2]), "r"(a[3]), "r"(b[0]), "r"(b[1]));
}

__global__ void __launch_bounds__(256, 2)
gemm_mma_kernel(const float* __restrict__ ent,
                const float* __restrict__ W_self,
                const float* __restrict__ b_self,
                const float* __restrict__ W_nei,
                const float* __restrict__ b_nei,
                float* __restrict__ out,
                int N) {
    extern __shared__ char smem[];
    uint32_t sb = smem_u32(smem);
    float* bias = (float*)(smem + SM_BIAS);

    int tid = threadIdx.x;
    int wid = tid >> 5;
    int lid = tid & 31;
    int wm = wid >> 2;            // 0-1 : 64-row slab
    int wn = wid & 3;             // 0-3 : 32-col slab
    int gid = lid >> 2;           // 0-7
    int tig = lid & 3;            // 0-3

    int row0 = blockIdx.x * 128;

    if (tid < 128) bias[tid] = b_self[tid] + b_nei[tid];

    // ---- cp.async tile loader -------------------------------------------
    // idx = j*256 + tid ; r = idx>>3 (0..127), f4 = idx&7 (16B quad in chunk)
    auto load_chunk = [&](int kc, int buf) {
        const float* asrc = (kc < 4) ? ent : (const float*)g_agg;
        int akoff = (kc & 3) * 32;
        const float* bsrc = (kc < 4) ? W_self : W_nei;
#pragma unroll
        for (int j = 0; j < 4; j++) {
            int idx = j * 256 + tid;
            int r = idx >> 3;
            int f4 = idx & 7;
            // A
            int arow = row0 + r;
            uint32_t ad = sb + SM_AS(buf) + (uint32_t)(r * PITCH + f4 * 4) * 4;
            const float* ag = asrc + (size_t)arow * DIM + akoff + f4 * 4;
            CP_ASYNC(ad, ag, (arow < N) ? 16 : 0);
            // B (weights: row r = output o, no OOB)
            uint32_t bd = sb + SM_BS(buf) + (uint32_t)(r * PITCH + f4 * 4) * 4;
            const float* bg = bsrc + (size_t)r * DIM + akoff + f4 * 4;
            CP_ASYNC(bd, bg, 16);
        }
        CP_COMMIT();
    };

    load_chunk(0, 0);

    float acc[4][4][4];
#pragma unroll
    for (int mt = 0; mt < 4; mt++)
#pragma unroll
        for (int nt = 0; nt < 4; nt++)
#pragma unroll
            for (int j = 0; j < 4; j++) acc[mt][nt][j] = 0.f;

    for (int kc = 0; kc < 8; kc++) {
        int buf = kc & 1;
        if (kc < 7) load_chunk(kc + 1, buf ^ 1);
        if (kc < 7) { CP_WAIT(1); } else { CP_WAIT(0); }
        __syncthreads();

        const float* As = (const float*)(smem + SM_AS(buf));
        const float* Bs = (const float*)(smem + SM_BS(buf));

#pragma unroll
        for (int s = 0; s < 4; s++) {
            uint32_t a[4][4], b[4][2];
#pragma unroll
            for (int mt = 0; mt < 4; mt++) {
                int r = wm * 64 + mt * 16 + gid;
                int c = s * 8 + tig;
                a[mt][0] = f2tf32(As[r * PITCH + c]);
                a[mt][1] = f2tf32(As[(r + 8) * PITCH + c]);
                a[mt][2] = f2tf32(As[r * PITCH + c + 4]);
                a[mt][3] = f2tf32(As[(r + 8) * PITCH + c + 4]);
            }
#pragma unroll
            for (int nt = 0; nt < 4; nt++) {
                int n = wn * 32 + nt * 8 + gid;
                int k = s * 8 + tig;
                b[nt][0] = f2tf32(Bs[n * PITCH + k]);
                b[nt][1] = f2tf32(Bs[n * PITCH + k + 4]);
            }
#pragma unroll
            for (int mt = 0; mt < 4; mt++)
#pragma unroll
                for (int nt = 0; nt < 4; nt++)
                    mma_tf32(acc[mt][nt], a[mt], b[nt]);
        }
        __syncthreads();
    }

    // ---- epilogue: bias + relu + store ----------------------------------
#pragma unroll
    for (int nt = 0; nt < 4; nt++) {
        int col = wn * 32 + nt * 8 + 2 * tig;
        float b0 = bias[col], b1 = bias[col + 1];
#pragma unroll
        for (int mt = 0; mt < 4; mt++) {
            int r1 = row0 + wm * 64 + mt * 16 + gid;
            int r2 = r1 + 8;
            float* d = acc[mt][nt];
            if (r1 < N) {
                float2 v = make_float2(fmaxf(d[0] + b0, 0.f),
                                       fmaxf(d[1] + b1, 0.f));
                *(float2*)&out[(size_t)r1 * DIM + col] = v;
            }
            if (r2 < N) {
                float2 v = make_float2(fmaxf(d[2] + b0, 0.f),
                                       fmaxf(d[3] + b1, 0.f));
                *(float2*)&out[(size_t)r2 * DIM + col] = v;
            }
        }
    }
}

// ============================================================================
// Launch. Inputs: ent, rel, edge_index(int32 [2,E]), edge_type(int32 [E]),
// W_self, b_self, W_nei, b_nei, W_rel, b_rel.
// Output: out_ent [N,128] then out_rel [R,128].
// ============================================================================
extern "C" void kernel_launch(void* const* d_in, const int* in_sizes, int n_in,
                              void* d_out, int out_size) {
    const float* ent    = (const float*)d_in[0];
    const float* rel    = (const float*)d_in[1];
    const int* eidx     = (const int*)d_in[2];
    const int* etype    = (const int*)d_in[3];
    const float* W_self = (const float*)d_in[4];
    const float* b_self = (const float*)d_in[5];
    const float* W_nei  = (const float*)d_in[6];
    const float* b_nei  = (const float*)d_in[7];
    const float* W_rel  = (const float*)d_in[8];
    const float* b_rel  = (const float*)d_in[9];

    int N = in_sizes[0] / DIM;   // 100000
    int R = in_sizes[1] / DIM;   // 500
    int E = in_sizes[3];         // 600000

    float* out_ent = (float*)d_out;
    float* out_rel = (float*)d_out + (size_t)N * DIM;

    int n4 = N * (DIM / 4);
    zero_agg_kernel<<<1024, 256>>>(n4);

    rel_kernel<<<R, DIM>>>(rel, W_rel, b_rel, out_rel);

    int edge_blocks = (E * 32 + 255) / 256;
    edge_kernel<<<edge_blocks, 256>>>(ent, eidx, etype, E);

    static int smem_set = 0;
    if (!smem_set) {
        cudaFuncSetAttribute(gemm_mma_kernel,
                             cudaFuncAttributeMaxDynamicSharedMemorySize,
                             GEMM_SMEM);
        smem_set = 1;
    }
    int gemm_blocks = (N + 127) / 128;   // 782
    gemm_mma_kernel<<<gemm_blocks, 256, GEMM_SMEM>>>(
        ent, W_self, b_self, W_nei, b_nei, out_ent, N);
}